// round 14
// baseline (speedup 1.0000x reference)
#include <cuda_runtime.h>
#include <cstdint>

#define NTIME   4096
#define NBATCH  4096
#define NEXTRA  256
#define COLS    8
#define THREADS 512
#define OPT     4                  // queries per thread (2048 per CTA)
#define NTAB    2048               // table entry p -> times[2p]
#define TAB_BYTES (NTAB * COLS * 4)   // 64 KB

__device__ __forceinline__ uint32_t smem_u32(const void* p) {
    uint32_t a;
    asm("{ .reg .u64 t; cvta.to.shared.u64 t, %1; cvt.u32.u64 %0, t; }"
        : "=r"(a) : "l"(p));
    return a;
}

__global__ __launch_bounds__(THREADS, 3)
void interp_kernel(const float* __restrict__ times,
                   const float* __restrict__ values,
                   const float* __restrict__ t,
                   float* __restrict__ out)
{
    extern __shared__ __align__(16) float table[];   // [NTAB][COLS], row-major, 64 KB
    __shared__ __align__(8) unsigned long long mbar;

    const int b0  = blockIdx.x * COLS;
    const int tid = threadIdx.x;
    const uint32_t mb = smem_u32(&mbar);

    if (tid == 0)
        asm volatile("mbarrier.init.shared.b64 [%0], %1;" :: "r"(mb), "r"(THREADS) : "memory");
    __syncthreads();

    // ---- Stage coarse table via cp.async.bulk: 4 ops x 32B per thread (0 SM wavefronts)
    asm volatile("mbarrier.arrive.expect_tx.shared.b64 _, [%0], %1;"
                 :: "r"(mb), "r"(4u * 32u) : "memory");
    #pragma unroll
    for (int i = 0; i < 4; i++) {
        int e = tid + i * THREADS;                       // table row, covers times row 2e
        const float* src = times + (size_t)(2 * e) * NBATCH + b0;   // 32B, 32B-aligned
        uint32_t dst = smem_u32(table + e * COLS);
        asm volatile(
            "cp.async.bulk.shared::cluster.global.mbarrier::complete_tx::bytes "
            "[%0], [%1], %2, [%3];"
            :: "r"(dst), "l"(src), "r"(32u), "r"(mb) : "memory");
    }

    // ---- Per-thread query setup (overlaps with staging) ----
    const int c    = tid & (COLS - 1);
    const int qb   = tid >> 3;                  // +64 per k
    const int bcol = b0 + c;

    int   oidx[OPT];
    float tq[OPT];
    #pragma unroll
    for (int k = 0; k < OPT; k++) {
        int q   = qb + k * (THREADS / COLS);
        oidx[k] = q * NBATCH + bcol;
        tq[k]   = t[oidx[k]];
    }

    // ---- Wait for table (acquire) ----
    {
        uint32_t done;
        asm volatile(
            "{\n\t.reg .pred p;\n\t"
            "mbarrier.try_wait.parity.acquire.cta.shared::cta.b64 p, [%1], 0;\n\t"
            "selp.b32 %0, 1, 0, p;\n\t}"
            : "=r"(done) : "r"(mb) : "memory");
        if (!done) {
            asm volatile(
                "{\n\t.reg .pred P1;\n\t"
                "WL_%=:\n\t"
                "mbarrier.try_wait.parity.acquire.cta.shared::cta.b64 P1, [%0], 0, 0x989680;\n\t"
                "@P1 bra.uni WD_%=;\n\t"
                "bra.uni WL_%=;\n\t"
                "WD_%=:\n\t}"
                :: "r"(mb) : "memory");
        }
    }

    // ---- Coarse: interpolation search on SMEM table T[p] = times[2p] ----
    // Result: p = max{p : T[p] <= tq}, alo = T[p], ahi = T[p+1] (if p < NTAB-1).
    #define TB(pp) table[(pp) * COLS + c]
    const float tTop = TB(NTAB - 1);

    int   lo[OPT], hi[OPT];
    float alo[OPT], ahi[OPT];
    #pragma unroll
    for (int k = 0; k < OPT; k++) {
        if (tTop <= tq[k]) {                    // p = NTAB-1 (j odd -> wrap path only)
            lo[k] = NTAB - 1; hi[k] = NTAB - 1;
            alo[k] = tTop;    ahi[k] = tTop;
        } else {
            lo[k] = 0;        hi[k] = NTAB - 1;
            alo[k] = TB(0);   ahi[k] = tTop;
        }
    }
    #pragma unroll
    for (int it = 0; it < 3; it++) {            // batched interp iterations (near-linear data)
        #pragma unroll
        for (int k = 0; k < OPT; k++) {
            if (hi[k] - lo[k] > 1) {
                float frac = __fdividef(tq[k] - alo[k], ahi[k] - alo[k]);
                int   m    = lo[k] + 1 + (int)(frac * (float)(hi[k] - lo[k] - 1));
                m = min(max(m, lo[k] + 1), hi[k] - 1);
                float am = TB(m);
                bool  le = (am <= tq[k]);
                lo[k]  = le ? m  : lo[k];
                alo[k] = le ? am : alo[k];
                hi[k]  = le ? hi[k] : m;
                ahi[k] = le ? ahi[k] : am;
            }
        }
    }
    #pragma unroll
    for (int k = 0; k < OPT; k++) {             // guaranteed-terminating cleanup
        while (hi[k] - lo[k] > 1) {
            int   m  = (lo[k] + hi[k]) >> 1;
            float am = TB(m);
            if (am <= tq[k]) { lo[k] = m; alo[k] = am; }
            else             { hi[k] = m; ahi[k] = am; }
        }
    }
    #undef TB

    // ---- Fine: ONE scattered probe times[2p+1] resolves j exactly ----
    int   r[OPT];
    float am[OPT];
    #pragma unroll
    for (int k = 0; k < OPT; k++) {
        r[k]  = 2 * lo[k] + 1;                  // p=NTAB-1 -> r=4095 (last row)
        am[k] = __ldg(times + (size_t)r[k] * NBATCH + bcol);
    }

    // ---- Gather values (2 scattered LDGs) & interpolate ----
    int   sidx[OPT];
    bool  wrap[OPT], odd[OPT];
    float vlo[OPT], vhi[OPT];
    #pragma unroll
    for (int k = 0; k < OPT; k++) {
        int j   = (am[k] <= tq[k]) ? r[k] : r[k] - 1;   // last index with times[j] <= tq
        wrap[k] = (j == NTIME - 1);             // count==NTIME -> torch -1 wrap
        odd[k]  = (j & 1) != 0;
        sidx[k] = wrap[k] ? (NTIME - 2) : j;
        vlo[k]  = __ldg(values + (size_t)sidx[k] * NBATCH + bcol);
        vhi[k]  = __ldg(values + (size_t)(sidx[k] + 1) * NBATCH + bcol);
    }
    #pragma unroll
    for (int k = 0; k < OPT; k++) {
        float tlo, thi;
        if (odd[k] && !wrap[k]) { tlo = am[k];  thi = ahi[k]; }  // j=2p+1: times[j]=am, times[j+1]=T[p+1]
        else                    { tlo = alo[k]; thi = am[k];  }  // j=2p (tlo=T[p]) or wrap (times[4094],times[4095])
        float t0 = wrap[k] ? thi : tlo;
        float v0 = wrap[k] ? vhi[k] : vlo[k];
        float s0 = (vhi[k] - vlo[k]) / (thi - tlo);
        out[oidx[k]] = v0 + s0 * (tq[k] - t0);
    }
}

extern "C" void kernel_launch(void* const* d_in, const int* in_sizes, int n_in,
                              void* d_out, int out_size)
{
    const float* times  = (const float*)d_in[0];
    const float* values = (const float*)d_in[1];
    const float* t      = (const float*)d_in[2];
    float*       out    = (float*)d_out;

    cudaFuncSetAttribute(interp_kernel,
                         cudaFuncAttributeMaxDynamicSharedMemorySize, TAB_BYTES);
    interp_kernel<<<NBATCH / COLS, THREADS, TAB_BYTES>>>(times, values, t, out);
}